// round 4
// baseline (speedup 1.0000x reference)
#include <cuda_runtime.h>
#include <math.h>

#define BATCH 32
#define LQ 1024
#define LA 1024
#define HDIM 512

#define BM 128
#define BN 128
#define BK 32
#define KSTEPS (BK / 8)
#define LDST 132   // smem row stride in floats (128 + 4 pad) -> conflict-free frag loads

// Scratch (device globals: allocation inside kernel_launch is forbidden)
__device__ float    g_qU[(size_t)BATCH * LQ * HDIM];   // 64 MB
__device__ float    g_rowAtt[BATCH * LQ];
__device__ unsigned g_colMaxBits[BATCH * LA];          // float bits, values >= 0
__device__ float    g_colSum[BATCH * LA];

// ---------------------------------------------------------------------------
__device__ __forceinline__ unsigned cvt_tf32(float x) {
    unsigned u;
    asm("cvt.rna.tf32.f32 %0, %1;" : "=r"(u) : "f"(x));
    return u;
}

__device__ __forceinline__ void mma_tf32(float* d, const unsigned* a, const unsigned* b) {
    asm volatile(
        "mma.sync.aligned.m16n8k8.row.col.f32.tf32.tf32.f32 "
        "{%0,%1,%2,%3}, {%4,%5,%6,%7}, {%8,%9}, {%0,%1,%2,%3};\n"
        : "+f"(d[0]), "+f"(d[1]), "+f"(d[2]), "+f"(d[3])
        : "r"(a[0]), "r"(a[1]), "r"(a[2]), "r"(a[3]), "r"(b[0]), "r"(b[1]));
}

// Transposed tile load: global [row][k] row-major (ldg) -> smem [k][row], tf32-rounded.
// 256 threads; 2 threads per row cover 8 consecutive k (full 32B sectors).
__device__ __forceinline__ void load_tile_T(float* sm, const float* g, int ldg, int tid) {
    const int row = tid >> 1;          // 0..127
    const int kb  = (tid & 1) * 4;     // 0 or 4
    float4 v[4];
    #pragma unroll
    for (int kk = 0; kk < 4; kk++)
        v[kk] = *(const float4*)(g + (size_t)row * ldg + kk * 8 + kb);
    #pragma unroll
    for (int kk = 0; kk < 4; kk++) {
        int k = kk * 8 + kb;
        sm[(k + 0) * LDST + row] = __uint_as_float(cvt_tf32(v[kk].x));
        sm[(k + 1) * LDST + row] = __uint_as_float(cvt_tf32(v[kk].y));
        sm[(k + 2) * LDST + row] = __uint_as_float(cvt_tf32(v[kk].z));
        sm[(k + 3) * LDST + row] = __uint_as_float(cvt_tf32(v[kk].w));
    }
}

// Direct tile load for U: global [k][n] row-major (HDIM) -> smem [k][n], tf32-rounded.
__device__ __forceinline__ void load_tile_U(float* sm, const float* g, int tid) {
    const int k  = tid >> 3;           // 0..31
    const int nb = (tid & 7) * 4;      // 0..28
    #pragma unroll
    for (int ii = 0; ii < 4; ii++) {
        int n = nb + ii * 32;
        float4 v = *(const float4*)(g + (size_t)k * HDIM + n);
        float4 w;
        w.x = __uint_as_float(cvt_tf32(v.x));
        w.y = __uint_as_float(cvt_tf32(v.y));
        w.z = __uint_as_float(cvt_tf32(v.z));
        w.w = __uint_as_float(cvt_tf32(v.w));
        *(float4*)(sm + k * LDST + n) = w;
    }
}

// Core mma over one BK tile. Warp grid 2x4 (wm x wn); warp tile 64x32.
// k-permutation: frag k-col c maps to data k 2c, c+4 -> 2c+1 (same for A and B).
__device__ __forceinline__ void compute_ktile(const float* sA, const float* sB,
                                              float acc[4][4][4], int wm, int wn, int lane) {
    const int c2 = 2 * (lane & 3);
    const int g4 = lane >> 2;
    #pragma unroll
    for (int ks = 0; ks < KSTEPS; ks++) {
        const int k2 = ks * 8 + c2;
        unsigned bfr[4][2];
        #pragma unroll
        for (int nt = 0; nt < 4; nt++) {
            int col = wn * 32 + nt * 8 + g4;
            bfr[nt][0] = __float_as_uint(sB[(k2 + 0) * LDST + col]);
            bfr[nt][1] = __float_as_uint(sB[(k2 + 1) * LDST + col]);
        }
        #pragma unroll
        for (int mt = 0; mt < 4; mt++) {
            int row = wm * 64 + mt * 16 + g4;
            unsigned afr[4];
            afr[0] = __float_as_uint(sA[(k2 + 0) * LDST + row]);
            afr[1] = __float_as_uint(sA[(k2 + 0) * LDST + row + 8]);
            afr[2] = __float_as_uint(sA[(k2 + 1) * LDST + row]);
            afr[3] = __float_as_uint(sA[(k2 + 1) * LDST + row + 8]);
            #pragma unroll
            for (int nt = 0; nt < 4; nt++)
                mma_tf32(acc[mt][nt], afr, bfr[nt]);
        }
    }
}

// ---------------------------------------------------------------------------
// Kernel 0: zero col-stat accumulators and the output buffer
// ---------------------------------------------------------------------------
__global__ void init_stats_kernel(float* out, int out_n) {
    int i = blockIdx.x * blockDim.x + threadIdx.x;
    if (i < BATCH * LA) {
        g_colMaxBits[i] = 0u;
        g_colSum[i] = 0.0f;
    }
    if (i < out_n) out[i] = 0.0f;
}

// ---------------------------------------------------------------------------
// Kernel 1: qU = q @ U  (tf32 tensor cores)
// ---------------------------------------------------------------------------
__global__ __launch_bounds__(256, 2) void gemm_qU_tc(const float* __restrict__ q,
                                                     const float* __restrict__ U) {
    __shared__ float sA[BK * LDST];
    __shared__ float sB[BK * LDST];
    const int tid  = threadIdx.x;
    const int lane = tid & 31;
    const int wm   = (tid >> 5) >> 2;
    const int wn   = (tid >> 5) & 3;
    const int m0   = blockIdx.y * BM;
    const int n0   = blockIdx.x * BN;

    float acc[4][4][4] = {};

    for (int kt = 0; kt < HDIM; kt += BK) {
        load_tile_T(sA, q + (size_t)m0 * HDIM + kt, HDIM, tid);
        load_tile_U(sB, U + (size_t)kt * HDIM + n0, tid);
        __syncthreads();
        compute_ktile(sA, sB, acc, wm, wn, lane);
        __syncthreads();
    }

    #pragma unroll
    for (int mt = 0; mt < 4; mt++) {
        int row = m0 + wm * 64 + mt * 16 + (lane >> 2);
        #pragma unroll
        for (int nt = 0; nt < 4; nt++) {
            int col = n0 + wn * 32 + nt * 8 + (lane & 3) * 2;
            *(float2*)(g_qU + (size_t)row * HDIM + col) =
                make_float2(acc[mt][nt][0], acc[mt][nt][1]);
            *(float2*)(g_qU + (size_t)(row + 8) * HDIM + col) =
                make_float2(acc[mt][nt][2], acc[mt][nt][3]);
        }
    }
}

// ---------------------------------------------------------------------------
// Kernel 2: fused X = qU @ a^T + sigmoid/exp + row & col softmax stats
// grid: (LQ/BM, BATCH); each block loops j-tiles over LA
// ---------------------------------------------------------------------------
__global__ __launch_bounds__(256, 2) void fused_X_tc(const float* __restrict__ a,
                                                     const float* __restrict__ q_mask,
                                                     const float* __restrict__ a_mask) {
    __shared__ float sA[BK * LDST];
    __shared__ float sB[BK * LDST];
    __shared__ float redM[4 * 128];
    __shared__ float redS[4 * 128];

    const int tid  = threadIdx.x;
    const int lane = tid & 31;
    const int wm   = (tid >> 5) >> 2;
    const int wn   = (tid >> 5) & 3;
    const int b    = blockIdx.y;
    const int i0   = blockIdx.x * BM;

    const float* qUb = g_qU + ((size_t)b * LQ + i0) * HDIM;
    const float* ab  = a + (size_t)b * LA * HDIM;

    // q_mask per owned row (rows: wm*64 + mt*16 + lane>>2 (+8))
    float qm[4][2];
    #pragma unroll
    for (int mt = 0; mt < 4; mt++) {
        int r = i0 + wm * 64 + mt * 16 + (lane >> 2);
        qm[mt][0] = q_mask[b * LQ + r];
        qm[mt][1] = q_mask[b * LQ + r + 8];
    }

    float rowMax[4][2] = {};   // I >= 0
    float rowSum[4][2] = {};

    for (int j0 = 0; j0 < LA; j0 += BN) {
        float acc[4][4][4] = {};
        for (int kt = 0; kt < HDIM; kt += BK) {
            load_tile_T(sA, qUb + kt, HDIM, tid);
            load_tile_T(sB, ab + (size_t)j0 * HDIM + kt, HDIM, tid);
            __syncthreads();
            compute_ktile(sA, sB, acc, wm, wn, lane);
            __syncthreads();
        }

        // ---- epilogue ----
        float am[4][2];
        #pragma unroll
        for (int nt = 0; nt < 4; nt++) {
            int c = j0 + wn * 32 + nt * 8 + (lane & 3) * 2;
            am[nt][0] = a_mask[b * LA + c];
            am[nt][1] = a_mask[b * LA + c + 1];
        }

        float cMax[4][2] = {};
        float cSum[4][2] = {};

        #pragma unroll
        for (int mt = 0; mt < 4; mt++) {
            #pragma unroll
            for (int nt = 0; nt < 4; nt++) {
                #pragma unroll
                for (int e = 0; e < 4; e++) {
                    // c-frag: e>>1 selects row (+8), e&1 selects col (+1)
                    float X = acc[mt][nt][e];
                    bool valid = (qm[mt][e >> 1] * am[nt][e & 1]) > 0.0f;
                    float I = valid ? __fdividef(1.0f, 1.0f + __expf(-X)) : 0.0f;
                    float ee = __expf(I);
                    rowMax[mt][e >> 1] = fmaxf(rowMax[mt][e >> 1], I);
                    rowSum[mt][e >> 1] += ee;
                    cMax[nt][e & 1] = fmaxf(cMax[nt][e & 1], I);
                    cSum[nt][e & 1] += ee;
                }
            }
        }

        // column reduce: butterfly over lane>>2 (cols repeat across these lanes)
        #pragma unroll
        for (int nt = 0; nt < 4; nt++) {
            #pragma unroll
            for (int j = 0; j < 2; j++) {
                float m = cMax[nt][j], s = cSum[nt][j];
                #pragma unroll
                for (int off = 4; off < 32; off <<= 1) {
                    m = fmaxf(m, __shfl_xor_sync(0xffffffffu, m, off));
                    s += __shfl_xor_sync(0xffffffffu, s, off);
                }
                if (lane < 4) {
                    int colL = wn * 32 + nt * 8 + 2 * lane + j;
                    redM[wm * 128 + colL] = m;
                    redS[wm * 128 + colL] = s;
                }
            }
        }
        __syncthreads();
        if (tid < 128) {
            float m = fmaxf(redM[tid], redM[128 + tid]);
            float s = redS[tid] + redS[128 + tid];
            int cj = b * LA + j0 + tid;
            atomicMax(&g_colMaxBits[cj], __float_as_uint(m));
            atomicAdd(&g_colSum[cj], s);
        }
        __syncthreads();
    }

    // row reduce: butterfly over lane&3 (rows repeat across these lanes)
    #pragma unroll
    for (int mt = 0; mt < 4; mt++) {
        #pragma unroll
        for (int e = 0; e < 2; e++) {
            float m = rowMax[mt][e], s = rowSum[mt][e];
            #pragma unroll
            for (int off = 1; off < 4; off <<= 1) {
                m = fmaxf(m, __shfl_xor_sync(0xffffffffu, m, off));
                s += __shfl_xor_sync(0xffffffffu, s, off);
            }
            if ((lane & 3) == 0) {
                int rowL = wm * 64 + mt * 16 + (lane >> 2) + e * 8;
                redM[wn * 128 + rowL] = m;
                redS[wn * 128 + rowL] = s;
            }
        }
    }
    __syncthreads();
    if (tid < 128) {
        float m = redM[tid], s = redS[tid];
        #pragma unroll
        for (int w = 1; w < 4; w++) {
            m = fmaxf(m, redM[w * 128 + tid]);
            s += redS[w * 128 + tid];
        }
        g_rowAtt[b * LQ + i0 + tid] = __expf(m) / s;
    }
}

// ---------------------------------------------------------------------------
// Kernel 3: weighted reductions, split over 4 L-segments with atomicAdd
// out layout: [q_attn (B*H), a_attn (B*H)]
// ---------------------------------------------------------------------------
__global__ __launch_bounds__(512) void finalize_tc(const float* __restrict__ q,
                                                   const float* __restrict__ a,
                                                   float* __restrict__ out) {
    __shared__ float attS[256];
    const int b     = blockIdx.x;
    const int which = blockIdx.y;   // 0 -> q_attn, 1 -> a_attn
    const int seg   = blockIdx.z;   // 0..3
    const int h     = threadIdx.x;  // 0..511
    const int l0    = seg * 256;

    if (h < 256) {
        int l = l0 + h;
        if (which == 0) {
            attS[h] = g_rowAtt[b * LQ + l];
        } else {
            float m = __uint_as_float(g_colMaxBits[b * LA + l]);
            attS[h] = __expf(m) / g_colSum[b * LA + l];
        }
    }
    __syncthreads();

    const float* src = ((which == 0) ? q : a) + (size_t)b * LQ * HDIM + (size_t)l0 * HDIM;

    float a0 = 0.f, a1 = 0.f, a2 = 0.f, a3 = 0.f;
    #pragma unroll 4
    for (int l = 0; l < 256; l += 4) {
        a0 = fmaf(src[(size_t)(l + 0) * HDIM + h], attS[l + 0], a0);
        a1 = fmaf(src[(size_t)(l + 1) * HDIM + h], attS[l + 1], a1);
        a2 = fmaf(src[(size_t)(l + 2) * HDIM + h], attS[l + 2], a2);
        a3 = fmaf(src[(size_t)(l + 3) * HDIM + h], attS[l + 3], a3);
    }
    atomicAdd(&out[(size_t)which * BATCH * HDIM + b * HDIM + h], (a0 + a1) + (a2 + a3));
}

// ---------------------------------------------------------------------------
extern "C" void kernel_launch(void* const* d_in, const int* in_sizes, int n_in,
                              void* d_out, int out_size) {
    const float* q      = (const float*)d_in[0];
    const float* a      = (const float*)d_in[1];
    const float* U      = (const float*)d_in[2];
    const float* q_mask = (const float*)d_in[3];
    const float* a_mask = (const float*)d_in[4];
    float* out = (float*)d_out;

    init_stats_kernel<<<(BATCH * LA + 255) / 256, 256>>>(out, out_size);

    dim3 g1(HDIM / BN, (BATCH * LQ) / BM);   // (4, 256)
    gemm_qU_tc<<<g1, 256>>>(q, U);

    dim3 g2(LQ / BM, BATCH);                 // (8, 32)
    fused_X_tc<<<g2, 256>>>(a, q_mask, a_mask);

    dim3 g3(BATCH, 2, 4);
    finalize_tc<<<g3, 512>>>(q, a, out);
}

// round 6
// speedup vs baseline: 1.1692x; 1.1692x over previous
#include <cuda_runtime.h>
#include <math.h>

#define BATCH 32
#define LQ 1024
#define LA 1024
#define HDIM 512

#define BM 128
#define BN 128
#define BK 32
#define NSTAGE 3
#define LDR 36                 // row-major tile stride (floats): 32 + 4 pad, 16B-aligned rows
#define LDU 132                // U tile [k][n] stride
#define TILE_F (BM * LDR)      // 4608 floats
#define UTILE_F (BK * LDU)     // 4224 floats
#define NKT (HDIM / BK)        // 16

// Scratch (device globals: allocation inside kernel_launch is forbidden)
__device__ float    g_qU[(size_t)BATCH * LQ * HDIM];   // 64 MB
__device__ float    g_rowAtt[BATCH * LQ];
__device__ unsigned g_colMaxBits[BATCH * LA];          // float bits, values >= 0
__device__ float    g_colSum[BATCH * LA];

// ---------------------------------------------------------------------------
__device__ __forceinline__ unsigned cvt_tf32(float x) {
    unsigned u;
    asm("cvt.rna.tf32.f32 %0, %1;" : "=r"(u) : "f"(x));
    return u;
}

__device__ __forceinline__ void mma_tf32(float* d, const unsigned* a, const unsigned* b) {
    asm volatile(
        "mma.sync.aligned.m16n8k8.row.col.f32.tf32.tf32.f32 "
        "{%0,%1,%2,%3}, {%4,%5,%6,%7}, {%8,%9}, {%0,%1,%2,%3};\n"
        : "+f"(d[0]), "+f"(d[1]), "+f"(d[2]), "+f"(d[3])
        : "r"(a[0]), "r"(a[1]), "r"(a[2]), "r"(a[3]), "r"(b[0]), "r"(b[1]));
}

__device__ __forceinline__ void cp_async16(float* smem_ptr, const float* gmem) {
    unsigned s = (unsigned)__cvta_generic_to_shared(smem_ptr);
    asm volatile("cp.async.cg.shared.global [%0], [%1], 16;\n" :: "r"(s), "l"(gmem));
}
#define CP_COMMIT() asm volatile("cp.async.commit_group;\n" ::: "memory")
#define CP_WAIT1()  asm volatile("cp.async.wait_group 1;\n" ::: "memory")

// Row-major tile load: 128 rows x 32 floats (ld = HDIM), 256 threads x 4 chunks of 16B
__device__ __forceinline__ void load_rows_async(float* sm, const float* g, int tid) {
    #pragma unroll
    for (int i = 0; i < 4; i++) {
        int c = tid + i * 256;         // 0..1023
        int row = c >> 3, kc = c & 7;  // 8 chunks per row
        cp_async16(sm + row * LDR + kc * 4, g + (size_t)row * HDIM + kc * 4);
    }
}

// U tile load: 32 rows(k) x 128 floats(n) (ld = HDIM)
__device__ __forceinline__ void load_U_async(float* sm, const float* g, int tid) {
    #pragma unroll
    for (int i = 0; i < 4; i++) {
        int c = tid + i * 256;
        int k = c >> 5, nc = c & 31;   // 32 chunks per row
        cp_async16(sm + k * LDU + nc * 4, g + (size_t)k * HDIM + nc * 4);
    }
}

// mma over one BK tile, both operands row-major [row][k] with k-permutation:
// frag k-col c -> data k 2c ; c+4 -> 2c+1 (applied to A and B identically)
__device__ __forceinline__ void compute_rr(const float* sA, const float* sB,
                                           float acc[4][4][4], int wm, int wn, int lane) {
    const int c2 = 2 * (lane & 3);
    const int g4 = lane >> 2;
    #pragma unroll
    for (int ks = 0; ks < 4; ks++) {
        const int k2 = ks * 8 + c2;
        unsigned bfr[4][2];
        #pragma unroll
        for (int nt = 0; nt < 4; nt++) {
            int col = wn * 32 + nt * 8 + g4;
            float2 bv = *(const float2*)(sB + col * LDR + k2);
            bfr[nt][0] = cvt_tf32(bv.x);
            bfr[nt][1] = cvt_tf32(bv.y);
        }
        #pragma unroll
        for (int mt = 0; mt < 4; mt++) {
            int row = wm * 64 + mt * 16 + g4;
            float2 lo = *(const float2*)(sA + row * LDR + k2);
            float2 hi = *(const float2*)(sA + (row + 8) * LDR + k2);
            unsigned afr[4] = {cvt_tf32(lo.x), cvt_tf32(hi.x), cvt_tf32(lo.y), cvt_tf32(hi.y)};
            #pragma unroll
            for (int nt = 0; nt < 4; nt++)
                mma_tf32(acc[mt][nt], afr, bfr[nt]);
        }
    }
}

// same but B from U layout [k][n] (bank-conflict-free: bank = 8c + g4)
__device__ __forceinline__ void compute_ru(const float* sA, const float* sU,
                                           float acc[4][4][4], int wm, int wn, int lane) {
    const int c2 = 2 * (lane & 3);
    const int g4 = lane >> 2;
    #pragma unroll
    for (int ks = 0; ks < 4; ks++) {
        const int k2 = ks * 8 + c2;
        unsigned bfr[4][2];
        #pragma unroll
        for (int nt = 0; nt < 4; nt++) {
            int col = wn * 32 + nt * 8 + g4;
            bfr[nt][0] = cvt_tf32(sU[(k2 + 0) * LDU + col]);
            bfr[nt][1] = cvt_tf32(sU[(k2 + 1) * LDU + col]);
        }
        #pragma unroll
        for (int mt = 0; mt < 4; mt++) {
            int row = wm * 64 + mt * 16 + g4;
            float2 lo = *(const float2*)(sA + row * LDR + k2);
            float2 hi = *(const float2*)(sA + (row + 8) * LDR + k2);
            unsigned afr[4] = {cvt_tf32(lo.x), cvt_tf32(hi.x), cvt_tf32(lo.y), cvt_tf32(hi.y)};
            #pragma unroll
            for (int nt = 0; nt < 4; nt++)
                mma_tf32(acc[mt][nt], afr, bfr[nt]);
        }
    }
}

// ---------------------------------------------------------------------------
__global__ void init_stats_kernel(float* out, int out_n) {
    int i = blockIdx.x * blockDim.x + threadIdx.x;
    if (i < BATCH * LA) {
        g_colMaxBits[i] = 0u;
        g_colSum[i] = 0.0f;
    }
    if (i < out_n) out[i] = 0.0f;
}

// ---------------------------------------------------------------------------
// Kernel 1: qU = q @ U  (tf32, 3-stage cp.async pipeline)
// ---------------------------------------------------------------------------
__global__ __launch_bounds__(256, 2) void gemm_qU_tc(const float* __restrict__ q,
                                                     const float* __restrict__ U) {
    extern __shared__ float dsm[];
    float* sA = dsm;                       // [NSTAGE][TILE_F]
    float* sU = dsm + NSTAGE * TILE_F;     // [NSTAGE][UTILE_F]

    const int tid  = threadIdx.x;
    const int lane = tid & 31;
    const int wm   = (tid >> 5) >> 2;
    const int wn   = (tid >> 5) & 3;
    const int m0   = blockIdx.y * BM;
    const int n0   = blockIdx.x * BN;

    const float* gA = q + (size_t)m0 * HDIM;
    const float* gU = U + n0;

    float acc[4][4][4] = {};

    #pragma unroll
    for (int s = 0; s < NSTAGE - 1; s++) {
        load_rows_async(sA + s * TILE_F, gA + s * BK, tid);
        load_U_async(sU + s * UTILE_F, gU + (size_t)s * BK * HDIM, tid);
        CP_COMMIT();
    }

    for (int kt = 0; kt < NKT; kt++) {
        CP_WAIT1();
        __syncthreads();
        int pf = kt + NSTAGE - 1;
        if (pf < NKT) {
            load_rows_async(sA + (pf % NSTAGE) * TILE_F, gA + pf * BK, tid);
            load_U_async(sU + (pf % NSTAGE) * UTILE_F, gU + (size_t)pf * BK * HDIM, tid);
        }
        CP_COMMIT();
        compute_ru(sA + (kt % NSTAGE) * TILE_F, sU + (kt % NSTAGE) * UTILE_F,
                   acc, wm, wn, lane);
    }

    #pragma unroll
    for (int mt = 0; mt < 4; mt++) {
        int row = m0 + wm * 64 + mt * 16 + (lane >> 2);
        #pragma unroll
        for (int nt = 0; nt < 4; nt++) {
            int col = n0 + wn * 32 + nt * 8 + (lane & 3) * 2;
            *(float2*)(g_qU + (size_t)row * HDIM + col) =
                make_float2(acc[mt][nt][0], acc[mt][nt][1]);
            *(float2*)(g_qU + (size_t)(row + 8) * HDIM + col) =
                make_float2(acc[mt][nt][2], acc[mt][nt][3]);
        }
    }
}

// ---------------------------------------------------------------------------
// Kernel 2: fused X = qU @ a^T + sigmoid/exp + row & col stats
// Flat 128-tile pipeline over (j0 x kt); epilogue every 16 tiles overlaps
// with the next j-tile's in-flight cp.async loads.
// ---------------------------------------------------------------------------
__global__ __launch_bounds__(256, 2) void fused_X_tc(const float* __restrict__ a,
                                                     const float* __restrict__ q_mask,
                                                     const float* __restrict__ a_mask) {
    extern __shared__ float dsm[];
    float* sA = dsm;
    float* sB = dsm + NSTAGE * TILE_F;

    const int tid  = threadIdx.x;
    const int lane = tid & 31;
    const int wm   = (tid >> 5) >> 2;
    const int wn   = (tid >> 5) & 3;
    const int b    = blockIdx.y;
    const int i0   = blockIdx.x * BM;

    const float* qUb = g_qU + ((size_t)b * LQ + i0) * HDIM;
    const float* ab  = a + (size_t)b * LA * HDIM;

    float qm[4][2];
    #pragma unroll
    for (int mt = 0; mt < 4; mt++) {
        int r = i0 + wm * 64 + mt * 16 + (lane >> 2);
        qm[mt][0] = q_mask[b * LQ + r];
        qm[mt][1] = q_mask[b * LQ + r + 8];
    }

    float rowMax[4][2] = {};
    float rowSum[4][2] = {};
    float acc[4][4][4] = {};

    const int NT = (LA / BN) * NKT;   // 128 total tiles

    // issue tile t into stage t % NSTAGE
    #pragma unroll 1
    for (int s = 0; s < NSTAGE - 1; s++) {
        load_rows_async(sA + s * TILE_F, qUb + s * BK, tid);
        load_rows_async(sB + s * TILE_F, ab + s * BK, tid);   // j = 0
        CP_COMMIT();
    }

    for (int t = 0; t < NT; t++) {
        CP_WAIT1();
        __syncthreads();
        int pf = t + NSTAGE - 1;
        if (pf < NT) {
            int pj = pf >> 4, pk = pf & 15;
            load_rows_async(sA + (pf % NSTAGE) * TILE_F, qUb + pk * BK, tid);
            load_rows_async(sB + (pf % NSTAGE) * TILE_F,
                            ab + (size_t)pj * BN * HDIM + pk * BK, tid);
        }
        CP_COMMIT();
        compute_rr(sA + (t % NSTAGE) * TILE_F, sB + (t % NSTAGE) * TILE_F,
                   acc, wm, wn, lane);

        if ((t & 15) == 15) {
            // ---- epilogue for j0 = (t>>4)*BN ----
            const int j0 = (t >> 4) * BN;
            // reduction scratch aliases the just-consumed stage (free until
            // iteration t+1 re-issues into it, which is after a syncthreads)
            float* redM = sA + (t % NSTAGE) * TILE_F;
            float* redS = redM + 512;

            float am[4][2];
            #pragma unroll
            for (int nt = 0; nt < 4; nt++) {
                int c = j0 + wn * 32 + nt * 8 + (lane & 3) * 2;
                am[nt][0] = a_mask[b * LA + c];
                am[nt][1] = a_mask[b * LA + c + 1];
            }

            float cMax[4][2] = {};
            float cSum[4][2] = {};

            #pragma unroll
            for (int mt = 0; mt < 4; mt++) {
                #pragma unroll
                for (int nt = 0; nt < 4; nt++) {
                    #pragma unroll
                    for (int e = 0; e < 4; e++) {
                        float X = acc[mt][nt][e];
                        bool valid = (qm[mt][e >> 1] * am[nt][e & 1]) > 0.0f;
                        float I = valid ? __fdividef(1.0f, 1.0f + __expf(-X)) : 0.0f;
                        float ee = __expf(I);
                        rowMax[mt][e >> 1] = fmaxf(rowMax[mt][e >> 1], I);
                        rowSum[mt][e >> 1] += ee;
                        cMax[nt][e & 1] = fmaxf(cMax[nt][e & 1], I);
                        cSum[nt][e & 1] += ee;
                        acc[mt][nt][e] = 0.0f;   // reset for next j-tile
                    }
                }
            }

            __syncthreads();   // stage consumed by all warps before reuse as scratch
            #pragma unroll
            for (int nt = 0; nt < 4; nt++) {
                #pragma unroll
                for (int j = 0; j < 2; j++) {
                    float m = cMax[nt][j], s = cSum[nt][j];
                    #pragma unroll
                    for (int off = 4; off < 32; off <<= 1) {
                        m = fmaxf(m, __shfl_xor_sync(0xffffffffu, m, off));
                        s += __shfl_xor_sync(0xffffffffu, s, off);
                    }
                    if (lane < 4) {
                        int colL = wn * 32 + nt * 8 + 2 * lane + j;
                        redM[wm * 128 + colL] = m;
                        redS[wm * 128 + colL] = s;
                    }
                }
            }
            __syncthreads();
            if (tid < 128) {
                float m = fmaxf(redM[tid], redM[128 + tid]);
                float s = redS[tid] + redS[128 + tid];
                int cj = b * LA + j0 + tid;
                atomicMax(&g_colMaxBits[cj], __float_as_uint(m));
                atomicAdd(&g_colSum[cj], s);
            }
            __syncthreads();   // scratch released before next iteration writes stage
        }
    }

    // ---- final row reduction ----
    {
        float* redM = sA;          // all cp.async complete; safe after sync above
        float* redS = sA + 512;
        #pragma unroll
        for (int mt = 0; mt < 4; mt++) {
            #pragma unroll
            for (int e = 0; e < 2; e++) {
                float m = rowMax[mt][e], s = rowSum[mt][e];
                #pragma unroll
                for (int off = 1; off < 4; off <<= 1) {
                    m = fmaxf(m, __shfl_xor_sync(0xffffffffu, m, off));
                    s += __shfl_xor_sync(0xffffffffu, s, off);
                }
                if ((lane & 3) == 0) {
                    int rowL = wm * 64 + mt * 16 + (lane >> 2) + e * 8;
                    redM[wn * 128 + rowL] = m;
                    redS[wn * 128 + rowL] = s;
                }
            }
        }
        __syncthreads();
        if (tid < 128) {
            float m = redM[tid], s = redS[tid];
            #pragma unroll
            for (int w = 1; w < 4; w++) {
                m = fmaxf(m, redM[w * 128 + tid]);
                s += redS[w * 128 + tid];
            }
            g_rowAtt[b * LQ + i0 + tid] = __expf(m) / s;
        }
    }
}

// ---------------------------------------------------------------------------
// Kernel 3: weighted reductions, 8 L-segments with atomicAdd
// ---------------------------------------------------------------------------
__global__ __launch_bounds__(512) void finalize_tc(const float* __restrict__ q,
                                                   const float* __restrict__ a,
                                                   float* __restrict__ out) {
    __shared__ float attS[128];
    const int b     = blockIdx.x;
    const int which = blockIdx.y;
    const int seg   = blockIdx.z;   // 0..7
    const int h     = threadIdx.x;
    const int l0    = seg * 128;

    if (h < 128) {
        int l = l0 + h;
        if (which == 0) {
            attS[h] = g_rowAtt[b * LQ + l];
        } else {
            float m = __uint_as_float(g_colMaxBits[b * LA + l]);
            attS[h] = __expf(m) / g_colSum[b * LA + l];
        }
    }
    __syncthreads();

    const float* src = ((which == 0) ? q : a) + (size_t)b * LQ * HDIM + (size_t)l0 * HDIM;

    float a0 = 0.f, a1 = 0.f, a2 = 0.f, a3 = 0.f;
    #pragma unroll 4
    for (int l = 0; l < 128; l += 4) {
        a0 = fmaf(src[(size_t)(l + 0) * HDIM + h], attS[l + 0], a0);
        a1 = fmaf(src[(size_t)(l + 1) * HDIM + h], attS[l + 1], a1);
        a2 = fmaf(src[(size_t)(l + 2) * HDIM + h], attS[l + 2], a2);
        a3 = fmaf(src[(size_t)(l + 3) * HDIM + h], attS[l + 3], a3);
    }
    atomicAdd(&out[(size_t)which * BATCH * HDIM + b * HDIM + h], (a0 + a1) + (a2 + a3));
}

// ---------------------------------------------------------------------------
extern "C" void kernel_launch(void* const* d_in, const int* in_sizes, int n_in,
                              void* d_out, int out_size) {
    const float* q      = (const float*)d_in[0];
    const float* a      = (const float*)d_in[1];
    const float* U      = (const float*)d_in[2];
    const float* q_mask = (const float*)d_in[3];
    const float* a_mask = (const float*)d_in[4];
    float* out = (float*)d_out;

    const int smem_qU = NSTAGE * (TILE_F + UTILE_F) * sizeof(float);   // 105984
    const int smem_fx = NSTAGE * (2 * TILE_F) * sizeof(float);         // 110592
    cudaFuncSetAttribute(gemm_qU_tc, cudaFuncAttributeMaxDynamicSharedMemorySize, smem_qU);
    cudaFuncSetAttribute(fused_X_tc, cudaFuncAttributeMaxDynamicSharedMemorySize, smem_fx);

    init_stats_kernel<<<(BATCH * LA + 255) / 256, 256>>>(out, out_size);

    dim3 g1(HDIM / BN, (BATCH * LQ) / BM);   // (4, 256)
    gemm_qU_tc<<<g1, 256, smem_qU>>>(q, U);

    dim3 g2(LQ / BM, BATCH);                 // (8, 32)
    fused_X_tc<<<g2, 256, smem_fx>>>(a, q_mask, a_mask);

    dim3 g3(BATCH, 2, 8);
    finalize_tc<<<g3, 512>>>(q, a, out);
}